// round 5
// baseline (speedup 1.0000x reference)
#include <cuda_runtime.h>
#include <math.h>

#define SS 4096
#define VV 2048
#define BB 8
#define LL 32
#define WW 8

// Scratch (no allocation allowed in kernel_launch)
__device__ float g_lse[SS];
__device__ float g_prior[SS];
__device__ float g_logp[SS * 7];
__device__ float g_smt[(size_t)VV * SS];   // transposed smoothed emissions: [v][s]
__device__ float g_emis[LL * BB * SS];     // all_emis, layout (l, b, s)

// ---------------------------------------------------------------------------
// K1: per-row logsumexp of emis_w (one warp per row, float4 vectorized)
// ---------------------------------------------------------------------------
__global__ void k_row_lse(const float* __restrict__ w) {
    int row  = blockIdx.x * 8 + (threadIdx.x >> 5);
    int lane = threadIdx.x & 31;
    const float4* r = (const float4*)(w + (size_t)row * VV);
    float m = -1e30f;
#pragma unroll
    for (int i = 0; i < 16; i++) {
        float4 v = r[lane + 32 * i];
        m = fmaxf(m, fmaxf(fmaxf(v.x, v.y), fmaxf(v.z, v.w)));
    }
#pragma unroll
    for (int o = 16; o; o >>= 1) m = fmaxf(m, __shfl_xor_sync(0xffffffffu, m, o));
    float s = 0.f;
#pragma unroll
    for (int i = 0; i < 16; i++) {
        float4 v = r[lane + 32 * i];
        s += __expf(v.x - m) + __expf(v.y - m) + __expf(v.z - m) + __expf(v.w - m);
    }
#pragma unroll
    for (int o = 16; o; o >>= 1) s += __shfl_xor_sync(0xffffffffu, s, o);
    if (lane == 0) g_lse[row] = m + __logf(s);
}

// ---------------------------------------------------------------------------
// K1b: prior log_softmax (single block of 1024)
// ---------------------------------------------------------------------------
__global__ void k_prior(const float* __restrict__ pw) {
    __shared__ float red[32];
    __shared__ float bval;
    int tid = threadIdx.x;
    float v[4];
#pragma unroll
    for (int i = 0; i < 4; i++) v[i] = pw[tid + i * 1024];
    float m = fmaxf(fmaxf(v[0], v[1]), fmaxf(v[2], v[3]));
#pragma unroll
    for (int o = 16; o; o >>= 1) m = fmaxf(m, __shfl_xor_sync(0xffffffffu, m, o));
    if ((tid & 31) == 0) red[tid >> 5] = m;
    __syncthreads();
    if (tid < 32) {
        float t = red[tid];
#pragma unroll
        for (int o = 16; o; o >>= 1) t = fmaxf(t, __shfl_xor_sync(0xffffffffu, t, o));
        if (tid == 0) bval = t;
    }
    __syncthreads();
    m = bval;
    float s = __expf(v[0] - m) + __expf(v[1] - m) + __expf(v[2] - m) + __expf(v[3] - m);
#pragma unroll
    for (int o = 16; o; o >>= 1) s += __shfl_xor_sync(0xffffffffu, s, o);
    if ((tid & 31) == 0) red[tid >> 5] = s;
    __syncthreads();
    if (tid < 32) {
        float t = red[tid];
#pragma unroll
        for (int o = 16; o; o >>= 1) t += __shfl_xor_sync(0xffffffffu, t, o);
        if (tid == 0) bval = t;
    }
    __syncthreads();
    float lse = m + __logf(bval);
#pragma unroll
    for (int i = 0; i < 4; i++) g_prior[tid + i * 1024] = v[i] - lse;
}

// ---------------------------------------------------------------------------
// K1c: transition log-probs, replicating the reference's positional masking:
// the m-th VALID target (in original offset order) gets weight column m,
// normalized over trans_w[j, 0:nv].
// ---------------------------------------------------------------------------
__global__ void k_tlogp(const float* __restrict__ tw) {
    int j = blockIdx.x * blockDim.x + threadIdx.x;
    if (j >= SS) return;
    int x = j & 15, y = (j >> 4) & 15, z = j >> 8;
    int v1 = (x < 15), v2 = (x > 0), v3 = (y < 15), v4 = (y > 0), v5 = (z < 15), v6 = (z < 14);
    int nv = 1 + v1 + v2 + v3 + v4 + v5 + v6;
    float w[7];
#pragma unroll
    for (int k = 0; k < 7; k++) w[k] = tw[j * 7 + k];
    float m = w[0];
#pragma unroll
    for (int k = 1; k < 7; k++) if (k < nv) m = fmaxf(m, w[k]);
    float s = 0.f;
#pragma unroll
    for (int k = 0; k < 7; k++) if (k < nv) s += __expf(w[k] - m);
    float lse = m + __logf(s);
    int p2 = 1 + v1;
    int p3 = p2 + v2;
    int p4 = p3 + v3;
    int p5 = p4 + v4;
    int p6 = p5 + v5;
    float* o = g_logp + j * 7;
    o[0] = w[0] - lse;
    o[1] = v1 ? w[1]  - lse : -1e30f;
    o[2] = v2 ? w[p2] - lse : -1e30f;
    o[3] = v3 ? w[p3] - lse : -1e30f;
    o[4] = v4 ? w[p4] - lse : -1e30f;
    o[5] = v5 ? w[p5] - lse : -1e30f;
    o[6] = v6 ? w[p6] - lse : -1e30f;
}

// ---------------------------------------------------------------------------
// K2: smoothed emissions, stored TRANSPOSED (SMT[v][s]) via smem tile.
// sm[s,v] = log(0.2 * sum over {self, y±1 clamp, x±1 clamp} of exp(w[n,v]-lse[n]))
// ---------------------------------------------------------------------------
__global__ void k_smt(const float* __restrict__ ew) {
    __shared__ float tile[32][33];
    int tx = threadIdx.x, ty = threadIdx.y;
    int v0 = blockIdx.x * 32;
    int s0 = blockIdx.y * 32;
#pragma unroll
    for (int i = 0; i < 4; i++) {
        int sl = ty + 8 * i;
        int s = s0 + sl;
        int x = s & 15, y = (s >> 4) & 15;
        int su = (y < 15) ? s + 16 : s;
        int sd = (y > 0)  ? s - 16 : s;
        int sp = (x < 15) ? s + 1  : s;
        int sm = (x > 0)  ? s - 1  : s;
        int v = v0 + tx;
        float q = __expf(ew[(size_t)su * VV + v] - g_lse[su])
                + __expf(ew[(size_t)sd * VV + v] - g_lse[sd])
                + __expf(ew[(size_t)sp * VV + v] - g_lse[sp])
                + __expf(ew[(size_t)sm * VV + v] - g_lse[sm])
                + __expf(ew[(size_t)s  * VV + v] - g_lse[s]);
        tile[tx][sl] = __logf(q * 0.2f);
    }
    __syncthreads();
#pragma unroll
    for (int i = 0; i < 4; i++) {
        int vl = ty + 8 * i;
        g_smt[(size_t)(v0 + vl) * SS + s0 + tx] = tile[vl][tx];
    }
}

// ---------------------------------------------------------------------------
// K3: all_emis[l,b,s] = sum_w SMT[tok][s]  (tok == V contributes 0)
// ---------------------------------------------------------------------------
__global__ void k_emis(const int* __restrict__ stories) {
    int s  = blockIdx.x * 256 + threadIdx.x;
    int lb = blockIdx.y;           // lb = l*8 + b
    int l = lb >> 3, b = lb & 7;
    const int* tk = stories + (b * LL + l) * WW;
    float acc = 0.f;
#pragma unroll
    for (int w = 0; w < WW; w++) {
        int t = __ldg(&tk[w]);
        if (t < VV) acc += g_smt[(size_t)t * SS + s];
    }
    g_emis[(size_t)lb * SS + s] = acc;
}

// ---------------------------------------------------------------------------
// K4: forward recurrence. One block per batch b, score kept in smem
// (double buffered), logp in registers, 32 steps with __syncthreads.
// ---------------------------------------------------------------------------
__global__ __launch_bounds__(1024, 1) void k_fwd(float* __restrict__ out) {
    __shared__ float buf0[SS];
    __shared__ float buf1[SS];
    int b = blockIdx.x;
    int tid = threadIdx.x;

    // preload transition logp into registers
    float lp[4][7];
#pragma unroll
    for (int i = 0; i < 4; i++) {
        int j = tid + i * 1024;
#pragma unroll
        for (int k = 0; k < 7; k++) lp[i][k] = g_logp[j * 7 + k];
    }

    // l = 0: score0 = emis[0,b,:] + prior
#pragma unroll
    for (int i = 0; i < 4; i++) {
        int j = tid + i * 1024;
        float v = g_emis[(size_t)b * SS + j] + g_prior[j];
        buf0[j] = v;
        out[(size_t)b * SS + j] = v;
    }
    __syncthreads();

    float* cur = buf0;
    float* nxt = buf1;
    for (int l = 1; l < LL; l++) {
        const float* em = g_emis + (size_t)(l * BB + b) * SS;
        float* o = out + (size_t)(l * BB + b) * SS;
#pragma unroll
        for (int i = 0; i < 4; i++) {
            int j = tid + i * 1024;
            int x = j & 15, y = (j >> 4) & 15, z = j >> 8;
            float t0 = cur[j] + lp[i][0];
            float t1 = cur[j + ((x < 15) ? 1 : 0)]   + lp[i][1];
            float t2 = cur[j - ((x > 0)  ? 1 : 0)]   + lp[i][2];
            float t3 = cur[j + ((y < 15) ? 16 : 0)]  + lp[i][3];
            float t4 = cur[j - ((y > 0)  ? 16 : 0)]  + lp[i][4];
            float t5 = cur[j + ((z < 15) ? 256 : 0)] + lp[i][5];
            float t6 = cur[j + ((z < 14) ? 512 : 0)] + lp[i][6];
            float m = fmaxf(fmaxf(fmaxf(t0, t1), fmaxf(t2, t3)),
                            fmaxf(fmaxf(t4, t5), t6));
            float ssum = __expf(t0 - m) + __expf(t1 - m) + __expf(t2 - m)
                       + __expf(t3 - m) + __expf(t4 - m) + __expf(t5 - m)
                       + __expf(t6 - m);
            float nv = em[j] + m + __logf(ssum);
            nxt[j] = nv;
            o[j] = nv;
        }
        __syncthreads();
        float* tmp = cur; cur = nxt; nxt = tmp;
    }
}

// ---------------------------------------------------------------------------
extern "C" void kernel_launch(void* const* d_in, const int* in_sizes, int n_in,
                              void* d_out, int out_size) {
    // Identify inputs by element count (robust to scalar story_length slot):
    // stories: 8*32*8=2048 (int32), trans_w: 4096*7=28672, emis_w: 4096*2048,
    // prior_w: 4096.
    const int*   stories = nullptr;
    const float* trans_w = nullptr;
    const float* emis_w  = nullptr;
    const float* prior_w = nullptr;
    for (int i = 0; i < n_in; i++) {
        switch (in_sizes[i]) {
            case 2048:            stories = (const int*)d_in[i];   break;
            case 28672:           trans_w = (const float*)d_in[i]; break;
            case SS * VV:         emis_w  = (const float*)d_in[i]; break;
            case SS:              prior_w = (const float*)d_in[i]; break;
            default: break;
        }
    }
    float* out = (float*)d_out;

    k_row_lse<<<512, 256>>>(emis_w);
    k_prior<<<1, 1024>>>(prior_w);
    k_tlogp<<<4, 1024>>>(trans_w);
    k_smt<<<dim3(VV / 32, SS / 32), dim3(32, 8)>>>(emis_w);
    k_emis<<<dim3(SS / 256, LL * BB), 256>>>(stories);
    k_fwd<<<BB, 1024>>>(out);
    (void)out_size;
}

// round 6
// speedup vs baseline: 1.1873x; 1.1873x over previous
#include <cuda_runtime.h>
#include <math.h>

#define SS 4096
#define VV 2048
#define BB 8
#define LL 32
#define WW 8
#define ZP 16

// Scratch (no allocation allowed in kernel_launch)
__device__ float g_lse[SS];
__device__ float g_prior[SS];
__device__ float g_logp[SS * 7];
__device__ float g_smt[(size_t)VV * SS];   // transposed smoothed emissions: [v][s]
__device__ float g_emis[LL * BB * SS];     // all_emis, layout (l, b, s)

// ---------------------------------------------------------------------------
// K1: per-row logsumexp of emis_w (one warp per row, float4 vectorized)
// ---------------------------------------------------------------------------
__global__ void k_row_lse(const float* __restrict__ w) {
    int row  = blockIdx.x * 8 + (threadIdx.x >> 5);
    int lane = threadIdx.x & 31;
    const float4* r = (const float4*)(w + (size_t)row * VV);
    float m = -1e30f;
#pragma unroll
    for (int i = 0; i < 16; i++) {
        float4 v = r[lane + 32 * i];
        m = fmaxf(m, fmaxf(fmaxf(v.x, v.y), fmaxf(v.z, v.w)));
    }
#pragma unroll
    for (int o = 16; o; o >>= 1) m = fmaxf(m, __shfl_xor_sync(0xffffffffu, m, o));
    float s = 0.f;
#pragma unroll
    for (int i = 0; i < 16; i++) {
        float4 v = r[lane + 32 * i];
        s += __expf(v.x - m) + __expf(v.y - m) + __expf(v.z - m) + __expf(v.w - m);
    }
#pragma unroll
    for (int o = 16; o; o >>= 1) s += __shfl_xor_sync(0xffffffffu, s, o);
    if (lane == 0) g_lse[row] = m + __logf(s);
}

// ---------------------------------------------------------------------------
// K1b: prior log_softmax (single block of 1024)
// ---------------------------------------------------------------------------
__global__ void k_prior(const float* __restrict__ pw) {
    __shared__ float red[32];
    __shared__ float bval;
    int tid = threadIdx.x;
    float v[4];
#pragma unroll
    for (int i = 0; i < 4; i++) v[i] = pw[tid + i * 1024];
    float m = fmaxf(fmaxf(v[0], v[1]), fmaxf(v[2], v[3]));
#pragma unroll
    for (int o = 16; o; o >>= 1) m = fmaxf(m, __shfl_xor_sync(0xffffffffu, m, o));
    if ((tid & 31) == 0) red[tid >> 5] = m;
    __syncthreads();
    if (tid < 32) {
        float t = red[tid];
#pragma unroll
        for (int o = 16; o; o >>= 1) t = fmaxf(t, __shfl_xor_sync(0xffffffffu, t, o));
        if (tid == 0) bval = t;
    }
    __syncthreads();
    m = bval;
    float s = __expf(v[0] - m) + __expf(v[1] - m) + __expf(v[2] - m) + __expf(v[3] - m);
#pragma unroll
    for (int o = 16; o; o >>= 1) s += __shfl_xor_sync(0xffffffffu, s, o);
    if ((tid & 31) == 0) red[tid >> 5] = s;
    __syncthreads();
    if (tid < 32) {
        float t = red[tid];
#pragma unroll
        for (int o = 16; o; o >>= 1) t += __shfl_xor_sync(0xffffffffu, t, o);
        if (tid == 0) bval = t;
    }
    __syncthreads();
    float lse = m + __logf(bval);
#pragma unroll
    for (int i = 0; i < 4; i++) g_prior[tid + i * 1024] = v[i] - lse;
}

// ---------------------------------------------------------------------------
// K1c: transition log-probs, replicating the reference's positional masking.
// ---------------------------------------------------------------------------
__global__ void k_tlogp(const float* __restrict__ tw) {
    int j = blockIdx.x * blockDim.x + threadIdx.x;
    if (j >= SS) return;
    int x = j & 15, y = (j >> 4) & 15, z = j >> 8;
    int v1 = (x < 15), v2 = (x > 0), v3 = (y < 15), v4 = (y > 0), v5 = (z < 15), v6 = (z < 14);
    int nv = 1 + v1 + v2 + v3 + v4 + v5 + v6;
    float w[7];
#pragma unroll
    for (int k = 0; k < 7; k++) w[k] = tw[j * 7 + k];
    float m = w[0];
#pragma unroll
    for (int k = 1; k < 7; k++) if (k < nv) m = fmaxf(m, w[k]);
    float s = 0.f;
#pragma unroll
    for (int k = 0; k < 7; k++) if (k < nv) s += __expf(w[k] - m);
    float lse = m + __logf(s);
    int p2 = 1 + v1;
    int p3 = p2 + v2;
    int p4 = p3 + v3;
    int p5 = p4 + v4;
    int p6 = p5 + v5;
    float* o = g_logp + j * 7;
    o[0] = w[0] - lse;
    o[1] = v1 ? w[1]  - lse : -1e30f;
    o[2] = v2 ? w[p2] - lse : -1e30f;
    o[3] = v3 ? w[p3] - lse : -1e30f;
    o[4] = v4 ? w[p4] - lse : -1e30f;
    o[5] = v5 ? w[p5] - lse : -1e30f;
    o[6] = v6 ? w[p6] - lse : -1e30f;
}

// ---------------------------------------------------------------------------
// K2: smoothed emissions, stored TRANSPOSED (SMT[v][s]).
// One block = one z-plane (256 states) x 32 vocab columns.
// Phase 1: P[s_local][v] = exp(w - lse)   (1 exp per element, computed ONCE)
// Phase 2: out = log(0.2 * (P[s]+P[x+1]+P[x-1]+P[y+16]+P[y-16]))  (1 log)
// ---------------------------------------------------------------------------
__global__ void k_smt(const float* __restrict__ ew) {
    __shared__ float P[256 * 33];
    __shared__ float slse[256];
    int tx = threadIdx.x, ty = threadIdx.y;     // 32 x 8
    int tid = ty * 32 + tx;
    int v0 = blockIdx.x * 32;
    int sbase = blockIdx.y * 256;               // z-plane

    slse[tid] = g_lse[sbase + tid];
    __syncthreads();

#pragma unroll
    for (int i = 0; i < 32; i++) {
        int sl = ty + 8 * i;
        float w = ew[(size_t)(sbase + sl) * VV + v0 + tx];
        P[sl * 33 + tx] = __expf(w - slse[sl]);
    }
    __syncthreads();

#pragma unroll
    for (int jb = 0; jb < 8; jb++) {
        int sl = jb * 32 + tx;
        int x = sl & 15, y = sl >> 4;
        int sxp = sl + (x < 15);
        int sxm = sl - (x > 0);
        int syp = sl + ((y < 15) ? 16 : 0);
        int sym = sl - ((y > 0)  ? 16 : 0);
#pragma unroll
        for (int k = 0; k < 4; k++) {
            int vl = ty + 8 * k;
            float q = P[sl * 33 + vl] + P[sxp * 33 + vl] + P[sxm * 33 + vl]
                    + P[syp * 33 + vl] + P[sym * 33 + vl];
            g_smt[(size_t)(v0 + vl) * SS + sbase + sl] = __logf(q * 0.2f);
        }
    }
}

// ---------------------------------------------------------------------------
// K3: all_emis[l,b,s] = sum_w SMT[tok][s]  (tok == V contributes 0)
// ---------------------------------------------------------------------------
__global__ void k_emis(const int* __restrict__ stories) {
    int s  = blockIdx.x * 256 + threadIdx.x;
    int lb = blockIdx.y;           // lb = l*8 + b
    int l = lb >> 3, b = lb & 7;
    const int* tk = stories + (b * LL + l) * WW;
    float acc = 0.f;
#pragma unroll
    for (int w = 0; w < WW; w++) {
        int t = __ldg(&tk[w]);
        if (t < VV) acc += g_smt[(size_t)t * SS + s];
    }
    g_emis[(size_t)lb * SS + s] = acc;
}

// ---------------------------------------------------------------------------
// K4: forward recurrence in probability space (mirrors the reference's own
// smax/amax-normalized formulation).
//   Pk[i][k] = exp(logp[i][k] - amax[i])   (invalid -> exactly 0, branchless)
//   per step: p[j] = exp(score[j] - smax)          -- 1 MUFU
//             q[i] = sum_k p[TGT[i,k]] * Pk[i][k]  -- 7 FMA, float4 gathers
//             new  = em + log(q) + smax + amax[i]  -- 1 MUFU
// One CTA per batch; 4 consecutive states per thread; scores in registers,
// p staged in smem; block max via two-level shuffle reduction.
// ---------------------------------------------------------------------------
__global__ __launch_bounds__(1024, 1) void k_fwd(float* __restrict__ out) {
    __shared__ float pbuf[SS];
    __shared__ float wmax[32];
    int b   = blockIdx.x;
    int tid = threadIdx.x;
    int wid = tid >> 5, lane = tid & 31;
    int j0 = tid * 4;
    int x0 = j0 & 15;          // 0,4,8,12
    int y  = (j0 >> 4) & 15;
    int z  = j0 >> 8;

    // Precompute per-state amax + renormalized transition probs (once).
    float Pk[4][7], am[4];
#pragma unroll
    for (int e = 0; e < 4; e++) {
        const float* lp = g_logp + (j0 + e) * 7;
        float l[7];
#pragma unroll
        for (int k = 0; k < 7; k++) l[k] = lp[k];
        float m = l[0];
#pragma unroll
        for (int k = 1; k < 7; k++) m = fmaxf(m, l[k]);
        am[e] = m;
#pragma unroll
        for (int k = 0; k < 7; k++) Pk[e][k] = __expf(l[k] - m);  // invalid -> 0
    }

    // l = 0: score0 = emis[0,b,:] + prior
    float4 emv = *(const float4*)(g_emis + (size_t)b * SS + j0);
    float4 prv = *(const float4*)(g_prior + j0);
    float sc[4];
    sc[0] = emv.x + prv.x; sc[1] = emv.y + prv.y;
    sc[2] = emv.z + prv.z; sc[3] = emv.w + prv.w;
    *(float4*)(out + (size_t)b * SS + j0) = make_float4(sc[0], sc[1], sc[2], sc[3]);

    // block max of scores
    float lm = fmaxf(fmaxf(sc[0], sc[1]), fmaxf(sc[2], sc[3]));
#pragma unroll
    for (int o = 16; o; o >>= 1) lm = fmaxf(lm, __shfl_xor_sync(0xffffffffu, lm, o));
    if (lane == 0) wmax[wid] = lm;
    __syncthreads();
    float smax = wmax[lane];
#pragma unroll
    for (int o = 16; o; o >>= 1) smax = fmaxf(smax, __shfl_xor_sync(0xffffffffu, smax, o));

    for (int l = 1; l < LL; l++) {
        // stage p = exp(score - smax)
        float4 p;
        p.x = __expf(sc[0] - smax); p.y = __expf(sc[1] - smax);
        p.z = __expf(sc[2] - smax); p.w = __expf(sc[3] - smax);
        *(float4*)(pbuf + j0) = p;
        __syncthreads();

        // gathers (clamped neighbors fall back to self; Pk==0 kills invalid)
        float cm1 = (x0 > 0)  ? pbuf[j0 - 1] : p.x;
        float cp4 = (x0 < 12) ? pbuf[j0 + 4] : p.w;
        float4 yp = (y < 15) ? *(const float4*)(pbuf + j0 + 16)  : p;
        float4 ym = (y > 0)  ? *(const float4*)(pbuf + j0 - 16)  : p;
        float4 zp = (z < 15) ? *(const float4*)(pbuf + j0 + 256) : p;
        float4 zq = (z < 14) ? *(const float4*)(pbuf + j0 + 512) : p;

        float pc[4]  = {p.x, p.y, p.z, p.w};
        float pxp[4] = {p.y, p.z, p.w, cp4};
        float pxm[4] = {cm1, p.x, p.y, p.z};
        float pyp[4] = {yp.x, yp.y, yp.z, yp.w};
        float pym[4] = {ym.x, ym.y, ym.z, ym.w};
        float pzp[4] = {zp.x, zp.y, zp.z, zp.w};
        float pzq[4] = {zq.x, zq.y, zq.z, zq.w};

        emv = *(const float4*)(g_emis + (size_t)(l * BB + b) * SS + j0);
        float emr[4] = {emv.x, emv.y, emv.z, emv.w};

        float lmn = -1e30f;
#pragma unroll
        for (int e = 0; e < 4; e++) {
            float q = pc[e]  * Pk[e][0];
            q = fmaf(pxp[e], Pk[e][1], q);
            q = fmaf(pxm[e], Pk[e][2], q);
            q = fmaf(pyp[e], Pk[e][3], q);
            q = fmaf(pym[e], Pk[e][4], q);
            q = fmaf(pzp[e], Pk[e][5], q);
            q = fmaf(pzq[e], Pk[e][6], q);
            sc[e] = emr[e] + __logf(q) + smax + am[e];
            lmn = fmaxf(lmn, sc[e]);
        }
        *(float4*)(out + (size_t)(l * BB + b) * SS + j0) =
            make_float4(sc[0], sc[1], sc[2], sc[3]);

        // block max for next step's normalizer
#pragma unroll
        for (int o = 16; o; o >>= 1) lmn = fmaxf(lmn, __shfl_xor_sync(0xffffffffu, lmn, o));
        if (lane == 0) wmax[wid] = lmn;
        __syncthreads();   // also guards pbuf reuse (WAR)
        smax = wmax[lane];
#pragma unroll
        for (int o = 16; o; o >>= 1) smax = fmaxf(smax, __shfl_xor_sync(0xffffffffu, smax, o));
    }
}

// ---------------------------------------------------------------------------
extern "C" void kernel_launch(void* const* d_in, const int* in_sizes, int n_in,
                              void* d_out, int out_size) {
    const int*   stories = nullptr;
    const float* trans_w = nullptr;
    const float* emis_w  = nullptr;
    const float* prior_w = nullptr;
    for (int i = 0; i < n_in; i++) {
        switch (in_sizes[i]) {
            case 2048:            stories = (const int*)d_in[i];   break;
            case 28672:           trans_w = (const float*)d_in[i]; break;
            case SS * VV:         emis_w  = (const float*)d_in[i]; break;
            case SS:              prior_w = (const float*)d_in[i]; break;
            default: break;
        }
    }
    float* out = (float*)d_out;

    k_row_lse<<<512, 256>>>(emis_w);
    k_prior<<<1, 1024>>>(prior_w);
    k_tlogp<<<4, 1024>>>(trans_w);
    k_smt<<<dim3(VV / 32, ZP), dim3(32, 8)>>>(emis_w);
    k_emis<<<dim3(SS / 256, LL * BB), 256>>>(stories);
    k_fwd<<<BB, 1024>>>(out);
    (void)out_size;
}